// round 4
// baseline (speedup 1.0000x reference)
#include <cuda_runtime.h>
#include <cuda_bf16.h>
#include <cstdint>

// Indexer gather: out[i, :] = items[min(floor(clamp(indices[i],0,1)*1024), 1023), :]
// indices: [1048576] f32, items: [1024, 256] f32, out: [1048576, 256] f32.
//
// R3: MLP=8. Each thread handles 8 independent float4 chunks at grid-span
// stride (perfect coalescing preserved). Deeper per-thread request queues
// (8 index loads -> 8 L2-hit gathers -> 8 streaming stores) to keep the
// L2->HBM write path saturated. Occupancy traded down (5 CTA/SM) for 25%
// more total in-flight memory ops.

static constexpr int N_INDICES   = 1048576;
static constexpr int D_ITEM      = 256;
static constexpr int N_ITEMS     = 1024;
static constexpr int VEC_PER_ROW = D_ITEM / 4;                                  // 64
static constexpr long long TOTAL_VEC = (long long)N_INDICES * VEC_PER_ROW;      // 2^26
static constexpr int ITERS   = 8;
static constexpr int THREADS = 256;
static constexpr unsigned SPAN = (unsigned)(TOTAL_VEC / ITERS);                 // 2^23

__global__ __launch_bounds__(THREADS, 5)
void indexer_gather_kernel(const float* __restrict__ indices,
                           const float4* __restrict__ items,
                           float4* __restrict__ out)
{
    unsigned tid = blockIdx.x * blockDim.x + threadIdx.x;   // < 2^23

    float xi[ITERS];
    #pragma unroll
    for (int i = 0; i < ITERS; i++) {
        xi[i] = __ldg(&indices[(tid + (unsigned)i * SPAN) >> 6]);  // 8 independent index loads
    }

    float4 val[ITERS];
    #pragma unroll
    for (int i = 0; i < ITERS; i++) {
        float x = fminf(fmaxf(xi[i], 0.0f), 1.0f) * (float)N_ITEMS;
        int closest = min((int)floorf(x), N_ITEMS - 1);
        unsigned col = (tid + (unsigned)i * SPAN) & 63u;
        val[i] = __ldg(&items[(unsigned)closest * VEC_PER_ROW + col]);  // 8 independent gathers
    }

    #pragma unroll
    for (int i = 0; i < ITERS; i++) {
        __stcs(&out[tid + (unsigned)i * SPAN], val[i]);  // 8 streaming stores
    }
}

extern "C" void kernel_launch(void* const* d_in, const int* in_sizes, int n_in,
                              void* d_out, int out_size)
{
    const float*  indices = (const float*)d_in[0];
    const float4* items   = (const float4*)d_in[1];
    float4*       out     = (float4*)d_out;

    const unsigned blocks = SPAN / THREADS;   // 32768
    indexer_gather_kernel<<<blocks, THREADS>>>(indices, items, out);
}

// round 5
// speedup vs baseline: 1.6476x; 1.6476x over previous
#include <cuda_runtime.h>
#include <cuda_bf16.h>
#include <cstdint>

// Indexer gather: out[i, :] = items[min(floor(clamp(indices[i],0,1)*1024), 1023), :]
// indices: [1048576] f32, items: [1024, 256] f32, out: [1048576, 256] f32.
//
// R4: ITERS=4, same-row layout. Each thread handles 4 float4 chunks of ONE
// output row (cols (tid&15) + 16*i), so only ONE index load per thread
// (L1-hit broadcast) feeding 4 independent L2-hit gathers + 4 streaming
// stores. vs R2: same gather MLP, ~37% fewer LDG wavefronts through L1tex
// (the 81.5%-utilized resource in R2). Stores stay fully coalesced: per
// instruction, lanes 0-15 and 16-31 each write a contiguous 256B segment.

static constexpr int N_INDICES   = 1048576;
static constexpr int D_ITEM      = 256;
static constexpr int N_ITEMS     = 1024;
static constexpr int VEC_PER_ROW = D_ITEM / 4;                                  // 64
static constexpr int ITERS   = 4;
static constexpr int THREADS = 256;
static constexpr long long TOTAL_THREADS = (long long)N_INDICES * (VEC_PER_ROW / ITERS); // 2^24

__global__ __launch_bounds__(THREADS, 8)
void indexer_gather_kernel(const float* __restrict__ indices,
                           const float4* __restrict__ items,
                           float4* __restrict__ out)
{
    unsigned tid = blockIdx.x * blockDim.x + threadIdx.x;   // < 2^24
    unsigned row = tid >> 4;          // output/index row   (< 2^20)
    unsigned c0  = tid & 15u;         // base float4 column

    // One index load per thread (broadcast within each 16-lane group, L1-hit).
    float x = __ldg(&indices[row]);
    x = fminf(fmaxf(x, 0.0f), 1.0f) * (float)N_ITEMS;
    int closest = min((int)floorf(x), N_ITEMS - 1);
    const float4* irow = items + (unsigned)closest * VEC_PER_ROW;

    float4 val[ITERS];
    #pragma unroll
    for (int i = 0; i < ITERS; i++) {
        val[i] = __ldg(&irow[c0 + 16u * i]);     // 4 independent L2-hit gathers
    }

    float4* orow = out + (unsigned long long)row * VEC_PER_ROW;
    #pragma unroll
    for (int i = 0; i < ITERS; i++) {
        __stcs(&orow[c0 + 16u * i], val[i]);     // streaming stores, fully coalesced
    }
}

extern "C" void kernel_launch(void* const* d_in, const int* in_sizes, int n_in,
                              void* d_out, int out_size)
{
    const float*  indices = (const float*)d_in[0];
    const float4* items   = (const float4*)d_in[1];
    float4*       out     = (float4*)d_out;

    const unsigned blocks = (unsigned)(TOTAL_THREADS / THREADS);   // 65536
    indexer_gather_kernel<<<blocks, THREADS>>>(indices, items, out);
}